// round 7
// baseline (speedup 1.0000x reference)
#include <cuda_runtime.h>
#include <cstdint>

#define BATCH 4
#define SEQ   2048
#define DIM   768
#define NH    12
#define HD    64
#define BH    (BATCH*NH)          // 48
#define MROWS (BATCH*SEQ)         // 8192
#define SCALE 0.125f
#define LOG2E 1.4426950408889634f

// Scratch (allocation-free rule: __device__ globals)
__device__ float g_Q[BH*SEQ*HD];
__device__ float g_K[BH*SEQ*HD];
__device__ float g_V[BH*SEQ*HD];
__device__ float g_AO[BATCH*SEQ*DIM];

__device__ __forceinline__ uint32_t smem_u32(const void* p) {
    uint32_t a;
    asm("{ .reg .u64 t; cvta.to.shared.u64 t, %1; cvt.u32.u64 %0, t; }"
        : "=r"(a) : "l"(p));
    return a;
}

__device__ __forceinline__ uint32_t f2tf32(float x) {
    uint32_t r;
    asm("cvt.rna.tf32.f32 %0, %1;" : "=r"(r) : "f"(x));
    return r;
}

__device__ __forceinline__ float ex2(float x) {   // single MUFU.EX2
    float r;
    asm("ex2.approx.ftz.f32 %0, %1;" : "=f"(r) : "f"(x));
    return r;
}

__device__ __forceinline__ void cpa16(uint32_t dst, const void* src) {
    asm volatile("cp.async.cg.shared.global [%0], [%1], 16;"
                 :: "r"(dst), "l"(src));
}
#define CP_COMMIT() asm volatile("cp.async.commit_group;" ::: "memory")
#define CP_WAIT1()  asm volatile("cp.async.wait_group 1;" ::: "memory")
#define CP_WAIT0()  asm volatile("cp.async.wait_group 0;" ::: "memory")

__device__ __forceinline__ void mma_tf32(float c[4], uint32_t a0, uint32_t a1,
                                         uint32_t a2, uint32_t a3,
                                         uint32_t b0, uint32_t b1) {
    asm volatile(
        "mma.sync.aligned.m16n8k8.row.col.f32.tf32.tf32.f32 "
        "{%0,%1,%2,%3}, {%4,%5,%6,%7}, {%8,%9}, {%0,%1,%2,%3};"
        : "+f"(c[0]), "+f"(c[1]), "+f"(c[2]), "+f"(c[3])
        : "r"(a0), "r"(a1), "r"(a2), "r"(a3), "r"(b0), "r"(b1));
}

// ---------------------------------------------------------------------------
// mma.sync tf32 NT GEMM, cp.async 3-stage ring, tf32 convert at fragment load.
// CTA 128x128, K-chunk 32, 8 warps, warp tile 64x32. One sync per chunk.
// ---------------------------------------------------------------------------
#define KT    32
#define SSTR  36
#define CH_WORDS  (128 * SSTR)           // one tensor tile
#define GBUF_WORDS (2 * CH_WORDS)        // A + B per stage
#define GSM_BYTES (3 * GBUF_WORDS * 4)   // 110592

__global__ __launch_bounds__(256) void gemm_mma(
    const float* __restrict__ Ain, const float* __restrict__ W,
    const float* __restrict__ bias, float* __restrict__ out, int mode)
{
    extern __shared__ float smf[];
    uint32_t sbase = smem_u32(smf);

    const float* A = Ain ? Ain : g_AO;
    int tid  = threadIdx.x;
    int w    = tid >> 5, lane = tid & 31;
    int gr   = lane >> 2, qc = lane & 3;
    int wm   = (w & 1) * 64;
    int wn   = (w >> 1) * 32;
    int bm   = blockIdx.x * 128;
    int bn   = blockIdx.y * 128;

    // Per-thread staging slots (loop-invariant).
    const float* ag[4]; const float* wg[4]; uint32_t soff[4];
    #pragma unroll
    for (int i = 0; i < 4; ++i) {
        int e   = tid + i * 256;
        int row = e >> 3;
        int ks4 = (e & 7) * 4;
        ag[i]   = A + (size_t)(bm + row) * DIM + ks4;
        wg[i]   = W + (size_t)(bn + row) * DIM + ks4;
        soff[i] = (uint32_t)(row * SSTR + ks4) * 4u;
    }

    float acc[4][4][4];
    #pragma unroll
    for (int mt = 0; mt < 4; ++mt)
        #pragma unroll
        for (int nt = 0; nt < 4; ++nt)
            #pragma unroll
            for (int i = 0; i < 4; ++i) acc[mt][nt][i] = 0.f;

    const int NC = DIM / KT;   // 24

    // Prologue: stage chunks 0 and 1.
    #pragma unroll
    for (int i = 0; i < 4; ++i) {
        cpa16(sbase + soff[i], ag[i]);
        cpa16(sbase + CH_WORDS * 4 + soff[i], wg[i]);
    }
    CP_COMMIT();
    #pragma unroll
    for (int i = 0; i < 4; ++i) {
        cpa16(sbase + GBUF_WORDS * 4 + soff[i], ag[i] + KT);
        cpa16(sbase + (GBUF_WORDS + CH_WORDS) * 4 + soff[i], wg[i] + KT);
    }
    CP_COMMIT();

    int buf = 0;
    for (int c = 0; c < NC; ++c) {
        if (c + 1 < NC) CP_WAIT1(); else CP_WAIT0();
        __syncthreads();

        if (c + 2 < NC) {
            int nb = buf + 2; if (nb >= 3) nb -= 3;
            uint32_t nbb = sbase + (uint32_t)nb * GBUF_WORDS * 4u;
            #pragma unroll
            for (int i = 0; i < 4; ++i) {
                cpa16(nbb + soff[i], ag[i] + (c + 2) * KT);
                cpa16(nbb + CH_WORDS * 4 + soff[i], wg[i] + (c + 2) * KT);
            }
            CP_COMMIT();
        }

        const float* As = smf + buf * GBUF_WORDS;
        const float* Bs = As + CH_WORDS;

        #pragma unroll
        for (int ks = 0; ks < KT / 8; ++ks) {
            int k0 = ks * 8;
            uint32_t af[4][4], bf[4][2];
            #pragma unroll
            for (int mt = 0; mt < 4; ++mt) {
                const float* p = As + (wm + mt * 16 + gr) * SSTR + k0 + qc;
                af[mt][0] = f2tf32(p[0]);
                af[mt][1] = f2tf32(p[8 * SSTR]);
                af[mt][2] = f2tf32(p[4]);
                af[mt][3] = f2tf32(p[8 * SSTR + 4]);
            }
            #pragma unroll
            for (int nt = 0; nt < 4; ++nt) {
                const float* p = Bs + (wn + nt * 8 + gr) * SSTR + k0 + qc;
                bf[nt][0] = f2tf32(p[0]);
                bf[nt][1] = f2tf32(p[4]);
            }
            #pragma unroll
            for (int mt = 0; mt < 4; ++mt)
                #pragma unroll
                for (int nt = 0; nt < 4; ++nt)
                    mma_tf32(acc[mt][nt], af[mt][0], af[mt][1], af[mt][2],
                             af[mt][3], bf[nt][0], bf[nt][1]);
        }
        if (++buf >= 3) buf -= 3;
    }

    int scol = bn + wn;
    if (mode == 0) {
        int s   = scol / DIM;
        int rem = scol % DIM;
        int h   = rem / HD;
        int d0  = rem % HD;
        float* dst = (s == 0) ? g_Q : (s == 1) ? g_K : g_V;
        #pragma unroll
        for (int mt = 0; mt < 4; ++mt) {
            int r0 = bm + wm + mt * 16 + gr;
            int b  = r0 >> 11, n = r0 & (SEQ - 1);
            float* base = dst + ((size_t)(b * NH + h) * SEQ + n) * HD;
            #pragma unroll
            for (int nt = 0; nt < 4; ++nt) {
                int d = d0 + nt * 8 + 2 * qc;
                *(float2*)(base + d) = make_float2(acc[mt][nt][0], acc[mt][nt][1]);
                *(float2*)(base + 8 * HD + d) = make_float2(acc[mt][nt][2], acc[mt][nt][3]);
            }
        }
    } else {
        #pragma unroll
        for (int mt = 0; mt < 4; ++mt) {
            int r0 = bm + wm + mt * 16 + gr;
            float* base = out + (size_t)r0 * DIM;
            #pragma unroll
            for (int nt = 0; nt < 4; ++nt) {
                int cb = scol + nt * 8 + 2 * qc;
                float2 bv = *(const float2*)(bias + cb);
                *(float2*)(base + cb) =
                    make_float2(acc[mt][nt][0] + bv.x, acc[mt][nt][1] + bv.y);
                *(float2*)(base + 8 * DIM + cb) =
                    make_float2(acc[mt][nt][2] + bv.x, acc[mt][nt][3] + bv.y);
            }
        }
    }
}

// ---------------------------------------------------------------------------
// Flash attention, mma.sync tf32, cp.async double-buffered K/V (raw fp32,
// cvt.rna at fragment load). V kept natural [key][dim]; PV B-gather is
// column-wise (2-way bank conflict, acceptable).
// ---------------------------------------------------------------------------
#define ABC  64
#define KSTR 68
#define KBUF_WORDS (64 * KSTR)                    // 4352
// layout: Kraw[2] | Vraw[2] | Ps[128*KSTR]
#define V_OFF   (2 * KBUF_WORDS)
#define P_OFF   (4 * KBUF_WORDS)
#define ATT_SMEM ((4 * KBUF_WORDS + 128 * KSTR) * 4)   // 104448 bytes

__global__ __launch_bounds__(256) void attn_mma()
{
    extern __shared__ float sh[];
    uint32_t sbase = smem_u32(sh);
    float* Ps = sh + P_OFF;

    int bh  = blockIdx.y;
    int q0  = blockIdx.x * 128;
    int tid = threadIdx.x;
    int w   = tid >> 5, lane = tid & 31;
    int gr  = lane >> 2, qc = lane & 3;
    int wm  = w * 16;

    const float* Qb = g_Q + ((size_t)bh * SEQ + q0) * HD;
    const float* Kb = g_K + (size_t)bh * SEQ * HD;
    const float* Vb = g_V + (size_t)bh * SEQ * HD;

    // Q fragments, pre-scaled by SCALE*log2e, tf32-rounded.
    const float qs = SCALE * LOG2E;
    int r0 = wm + gr;
    uint32_t qf[8][4];
    #pragma unroll
    for (int kt = 0; kt < 8; ++kt) {
        int c = kt * 8 + qc;
        qf[kt][0] = f2tf32(Qb[(size_t)r0 * HD + c] * qs);
        qf[kt][1] = f2tf32(Qb[(size_t)(r0 + 8) * HD + c] * qs);
        qf[kt][2] = f2tf32(Qb[(size_t)r0 * HD + c + 4] * qs);
        qf[kt][3] = f2tf32(Qb[(size_t)(r0 + 8) * HD + c + 4] * qs);
    }

    // Per-thread staging slots (same pattern for K and V, natural layout).
    const float* kg[4]; const float* vg[4]; uint32_t soff[4];
    #pragma unroll
    for (int i = 0; i < 4; ++i) {
        int slot = tid + i * 256;
        int key  = slot >> 4;
        int d4   = (slot & 15) * 4;
        kg[i]   = Kb + key * HD + d4;
        vg[i]   = Vb + key * HD + d4;
        soff[i] = (uint32_t)(key * KSTR + d4) * 4u;
    }

    float of[8][4];
    #pragma unroll
    for (int nt = 0; nt < 8; ++nt)
        #pragma unroll
        for (int i = 0; i < 4; ++i) of[nt][i] = 0.f;
    float m0 = -1e30f, m1 = -1e30f, l0 = 0.f, l1 = 0.f;

    const int NT = SEQ / ABC;   // 32

    // Prologue: stage tile 0 into buffer 0.
    #pragma unroll
    for (int i = 0; i < 4; ++i) {
        cpa16(sbase + soff[i], kg[i]);
        cpa16(sbase + V_OFF * 4 + soff[i], vg[i]);
    }
    CP_COMMIT();

    #pragma unroll 1
    for (int t = 0; t < NT; ++t) {
        // Stage tile t+1 into the other buffer (protected by sync#2 of t-1).
        if (t + 1 < NT) {
            uint32_t kb = sbase + (uint32_t)((t + 1) & 1) * KBUF_WORDS * 4u;
            size_t goff = (size_t)(t + 1) * ABC * HD;
            #pragma unroll
            for (int i = 0; i < 4; ++i) {
                cpa16(kb + soff[i], kg[i] + goff);
                cpa16(kb + V_OFF * 4 + soff[i], vg[i] + goff);
            }
            CP_COMMIT();
            CP_WAIT1();
        } else {
            CP_WAIT0();
        }
        __syncthreads();   // sync#1: tile t visible to all warps

        const float* Kt = sh + (t & 1) * KBUF_WORDS;
        const float* Vt = Kt + V_OFF;

        // S = Q K^T  (scores already in log2 units)
        float sf[8][4];
        #pragma unroll
        for (int nt = 0; nt < 8; ++nt)
            #pragma unroll
            for (int i = 0; i < 4; ++i) sf[nt][i] = 0.f;
        #pragma unroll
        for (int kt = 0; kt < 8; ++kt) {
            int k0 = kt * 8;
            #pragma unroll
            for (int nt = 0; nt < 8; ++nt) {
                const float* bp = Kt + (nt * 8 + gr) * KSTR + k0 + qc;
                mma_tf32(sf[nt], qf[kt][0], qf[kt][1], qf[kt][2], qf[kt][3],
                         f2tf32(bp[0]), f2tf32(bp[4]));
            }
        }

        // Online softmax (log2 domain, hardware ex2)
        float tm0 = -1e30f, tm1 = -1e30f;
        #pragma unroll
        for (int nt = 0; nt < 8; ++nt) {
            tm0 = fmaxf(tm0, fmaxf(sf[nt][0], sf[nt][1]));
            tm1 = fmaxf(tm1, fmaxf(sf[nt][2], sf[nt][3]));
        }
        tm0 = fmaxf(tm0, __shfl_xor_sync(0xffffffffu, tm0, 1));
        tm0 = fmaxf(tm0, __shfl_xor_sync(0xffffffffu, tm0, 2));
        tm1 = fmaxf(tm1, __shfl_xor_sync(0xffffffffu, tm1, 1));
        tm1 = fmaxf(tm1, __shfl_xor_sync(0xffffffffu, tm1, 2));

        float nm0 = fmaxf(m0, tm0), nm1 = fmaxf(m1, tm1);
        float c0 = ex2(m0 - nm0), c1 = ex2(m1 - nm1);
        m0 = nm0; m1 = nm1;

        float rs0 = 0.f, rs1 = 0.f;
        float* prow0 = Ps + (wm + gr) * KSTR + 2 * qc;
        float* prow1 = prow0 + 8 * KSTR;
        #pragma unroll
        for (int nt = 0; nt < 8; ++nt) {
            // Round p to tf32 BEFORE accumulating l so num/denom bias cancels.
            float p0 = __uint_as_float(f2tf32(ex2(sf[nt][0] - nm0)));
            float p1 = __uint_as_float(f2tf32(ex2(sf[nt][1] - nm0)));
            float p2 = __uint_as_float(f2tf32(ex2(sf[nt][2] - nm1)));
            float p3 = __uint_as_float(f2tf32(ex2(sf[nt][3] - nm1)));
            rs0 += p0 + p1;
            rs1 += p2 + p3;
            *(float2*)(prow0 + nt * 8) = make_float2(p0, p1);
            *(float2*)(prow1 + nt * 8) = make_float2(p2, p3);
        }
        rs0 += __shfl_xor_sync(0xffffffffu, rs0, 1);
        rs0 += __shfl_xor_sync(0xffffffffu, rs0, 2);
        rs1 += __shfl_xor_sync(0xffffffffu, rs1, 1);
        rs1 += __shfl_xor_sync(0xffffffffu, rs1, 2);
        l0 = l0 * c0 + rs0;
        l1 = l1 * c1 + rs1;

        #pragma unroll
        for (int nt = 0; nt < 8; ++nt) {
            of[nt][0] *= c0; of[nt][1] *= c0;
            of[nt][2] *= c1; of[nt][3] *= c1;
        }
        __syncwarp();   // P is warp-private

        // O += P V   (V natural [key][dim]: column gather, 2-way conflict)
        #pragma unroll
        for (int kt = 0; kt < 8; ++kt) {
            int k0 = kt * 8;
            const uint32_t* ap =
                (const uint32_t*)(Ps + (wm + gr) * KSTR + k0 + qc);
            uint32_t a0 = ap[0];
            uint32_t a1 = ap[8 * KSTR];
            uint32_t a2 = ap[4];
            uint32_t a3 = ap[8 * KSTR + 4];
            #pragma unroll
            for (int nt = 0; nt < 8; ++nt) {
                const float* vp = Vt + (k0 + qc) * KSTR + nt * 8 + gr;
                mma_tf32(of[nt], a0, a1, a2, a3,
                         f2tf32(vp[0]), f2tf32(vp[4 * KSTR]));
            }
        }
        __syncthreads();   // sync#2: all reads of this buffer done
    }

    // Epilogue
    float inv0 = 1.f / l0, inv1 = 1.f / l1;
    int b = bh / NH, h = bh % NH;
    int n0 = q0 + wm + gr;
    float* o0 = g_AO + ((size_t)(b * SEQ + n0)) * DIM + h * HD;
    float* o1 = g_AO + ((size_t)(b * SEQ + n0 + 8)) * DIM + h * HD;
    #pragma unroll
    for (int nt = 0; nt < 8; ++nt) {
        int d = nt * 8 + 2 * qc;
        *(float2*)(o0 + d) = make_float2(of[nt][0] * inv0, of[nt][1] * inv0);
        *(float2*)(o1 + d) = make_float2(of[nt][2] * inv1, of[nt][3] * inv1);
    }
}

// ---------------------------------------------------------------------------
extern "C" void kernel_launch(void* const* d_in, const int* in_sizes, int n_in,
                              void* d_out, int out_size)
{
    const float* x      = (const float*)d_in[0];
    const float* w_qkv  = (const float*)d_in[1];
    const float* w_proj = (const float*)d_in[2];
    const float* b_proj = (const float*)d_in[3];
    float* out = (float*)d_out;

    cudaFuncSetAttribute(gemm_mma, cudaFuncAttributeMaxDynamicSharedMemorySize,
                         GSM_BYTES);
    cudaFuncSetAttribute(attn_mma, cudaFuncAttributeMaxDynamicSharedMemorySize,
                         ATT_SMEM);

    gemm_mma<<<dim3(MROWS/128, 3*DIM/128), 256, GSM_BYTES>>>(x, w_qkv, nullptr, nullptr, 0);
    attn_mma<<<dim3(SEQ/128, BH), 256, ATT_SMEM>>>();
    gemm_mma<<<dim3(MROWS/128, DIM/128), 256, GSM_BYTES>>>(nullptr, w_proj, b_proj, out, 1);
}

// round 8
// speedup vs baseline: 1.0804x; 1.0804x over previous
#include <cuda_runtime.h>
#include <cstdint>

#define BATCH 4
#define SEQ   2048
#define DIM   768
#define NH    12
#define HD    64
#define BH    (BATCH*NH)          // 48
#define MROWS (BATCH*SEQ)         // 8192
#define SCALE 0.125f
#define LOG2E 1.4426950408889634f

// Scratch (allocation-free rule: __device__ globals)
__device__ float g_Q[BH*SEQ*HD];
__device__ float g_K[BH*SEQ*HD];
__device__ float g_V[BH*SEQ*HD];
__device__ float g_AO[BATCH*SEQ*DIM];
__device__ float g_Xr[MROWS*DIM];        // tf32-rounded x
__device__ float g_Wqkvr[3*DIM*DIM];     // tf32-rounded w_qkv
__device__ float g_Wprojr[DIM*DIM];      // tf32-rounded w_proj

__device__ __forceinline__ uint32_t smem_u32(const void* p) {
    uint32_t a;
    asm("{ .reg .u64 t; cvta.to.shared.u64 t, %1; cvt.u32.u64 %0, t; }"
        : "=r"(a) : "l"(p));
    return a;
}

__device__ __forceinline__ uint32_t f2tf32(float x) {
    uint32_t r;
    asm("cvt.rna.tf32.f32 %0, %1;" : "=r"(r) : "f"(x));
    return r;
}
__device__ __forceinline__ float rnaf(float x) {
    return __uint_as_float(f2tf32(x));
}

__device__ __forceinline__ float ex2(float x) {   // single MUFU.EX2
    float r;
    asm("ex2.approx.ftz.f32 %0, %1;" : "=f"(r) : "f"(x));
    return r;
}

__device__ __forceinline__ void cpa16(uint32_t dst, const void* src) {
    asm volatile("cp.async.cg.shared.global [%0], [%1], 16;"
                 :: "r"(dst), "l"(src));
}
#define CP_COMMIT() asm volatile("cp.async.commit_group;" ::: "memory")
#define CP_WAIT1()  asm volatile("cp.async.wait_group 1;" ::: "memory")
#define CP_WAIT0()  asm volatile("cp.async.wait_group 0;" ::: "memory")

__device__ __forceinline__ void mma_tf32(float c[4], uint32_t a0, uint32_t a1,
                                         uint32_t a2, uint32_t a3,
                                         uint32_t b0, uint32_t b1) {
    asm volatile(
        "mma.sync.aligned.m16n8k8.row.col.f32.tf32.tf32.f32 "
        "{%0,%1,%2,%3}, {%4,%5,%6,%7}, {%8,%9}, {%0,%1,%2,%3};"
        : "+f"(c[0]), "+f"(c[1]), "+f"(c[2]), "+f"(c[3])
        : "r"(a0), "r"(a1), "r"(a2), "r"(a3), "r"(b0), "r"(b1));
}

// ---------------------------------------------------------------------------
// Prep: elementwise tf32 rounding into scratch. which: 0=x, 1=w_qkv, 2=w_proj
// ---------------------------------------------------------------------------
__global__ __launch_bounds__(256) void round_k(const float* __restrict__ s,
                                               int n4, int which)
{
    float* d = (which == 0) ? g_Xr : (which == 1) ? g_Wqkvr : g_Wprojr;
    int i = blockIdx.x * 256 + threadIdx.x;
    if (i < n4) {
        float4 v = ((const float4*)s)[i];
        v.x = rnaf(v.x); v.y = rnaf(v.y); v.z = rnaf(v.z); v.w = rnaf(v.w);
        ((float4*)d)[i] = v;
    }
}

// ---------------------------------------------------------------------------
// mma.sync tf32 NT GEMM, cp.async 3-stage ring, operands pre-rounded:
// NO cvt anywhere in the mainloop. CTA 128x128, K-chunk 32, 8 warps.
// mode 0: g_Xr x g_Wqkvr -> scatter Q raw, K/V tf32-rounded.
// mode 1: g_AO x g_Wprojr -> out = C + bias.
// ---------------------------------------------------------------------------
#define KT    32
#define SSTR  36
#define CH_WORDS  (128 * SSTR)
#define GBUF_WORDS (2 * CH_WORDS)
#define GSM_BYTES (3 * GBUF_WORDS * 4)   // 110592

__global__ __launch_bounds__(256) void gemm_mma(
    const float* __restrict__ bias, float* __restrict__ out, int mode)
{
    extern __shared__ float smf[];
    uint32_t sbase = smem_u32(smf);

    const float* A = (mode == 0) ? g_Xr : g_AO;
    const float* W = (mode == 0) ? g_Wqkvr : g_Wprojr;
    int tid  = threadIdx.x;
    int w    = tid >> 5, lane = tid & 31;
    int gr   = lane >> 2, qc = lane & 3;
    int wm   = (w & 1) * 64;
    int wn   = (w >> 1) * 32;
    int bm   = blockIdx.x * 128;
    int bn   = blockIdx.y * 128;

    const float* ag[4]; const float* wg[4]; uint32_t soff[4];
    #pragma unroll
    for (int i = 0; i < 4; ++i) {
        int e   = tid + i * 256;
        int row = e >> 3;
        int ks4 = (e & 7) * 4;
        ag[i]   = A + (size_t)(bm + row) * DIM + ks4;
        wg[i]   = W + (size_t)(bn + row) * DIM + ks4;
        soff[i] = (uint32_t)(row * SSTR + ks4) * 4u;
    }

    float acc[4][4][4];
    #pragma unroll
    for (int mt = 0; mt < 4; ++mt)
        #pragma unroll
        for (int nt = 0; nt < 4; ++nt)
            #pragma unroll
            for (int i = 0; i < 4; ++i) acc[mt][nt][i] = 0.f;

    const int NC = DIM / KT;   // 24

    #pragma unroll
    for (int i = 0; i < 4; ++i) {
        cpa16(sbase + soff[i], ag[i]);
        cpa16(sbase + CH_WORDS * 4 + soff[i], wg[i]);
    }
    CP_COMMIT();
    #pragma unroll
    for (int i = 0; i < 4; ++i) {
        cpa16(sbase + GBUF_WORDS * 4 + soff[i], ag[i] + KT);
        cpa16(sbase + (GBUF_WORDS + CH_WORDS) * 4 + soff[i], wg[i] + KT);
    }
    CP_COMMIT();

    int buf = 0;
    for (int c = 0; c < NC; ++c) {
        if (c + 1 < NC) CP_WAIT1(); else CP_WAIT0();
        __syncthreads();

        if (c + 2 < NC) {
            int nb = buf + 2; if (nb >= 3) nb -= 3;
            uint32_t nbb = sbase + (uint32_t)nb * GBUF_WORDS * 4u;
            #pragma unroll
            for (int i = 0; i < 4; ++i) {
                cpa16(nbb + soff[i], ag[i] + (c + 2) * KT);
                cpa16(nbb + CH_WORDS * 4 + soff[i], wg[i] + (c + 2) * KT);
            }
            CP_COMMIT();
        }

        const uint32_t* As = (const uint32_t*)(smf + buf * GBUF_WORDS);
        const uint32_t* Bs = As + CH_WORDS;

        #pragma unroll
        for (int ks = 0; ks < KT / 8; ++ks) {
            int k0 = ks * 8;
            uint32_t af[4][4], bf[4][2];
            #pragma unroll
            for (int mt = 0; mt < 4; ++mt) {
                const uint32_t* p = As + (wm + mt * 16 + gr) * SSTR + k0 + qc;
                af[mt][0] = p[0];
                af[mt][1] = p[8 * SSTR];
                af[mt][2] = p[4];
                af[mt][3] = p[8 * SSTR + 4];
            }
            #pragma unroll
            for (int nt = 0; nt < 4; ++nt) {
                const uint32_t* p = Bs + (wn + nt * 8 + gr) * SSTR + k0 + qc;
                bf[nt][0] = p[0];
                bf[nt][1] = p[4];
            }
            #pragma unroll
            for (int mt = 0; mt < 4; ++mt)
                #pragma unroll
                for (int nt = 0; nt < 4; ++nt)
                    mma_tf32(acc[mt][nt], af[mt][0], af[mt][1], af[mt][2],
                             af[mt][3], bf[nt][0], bf[nt][1]);
        }
        if (++buf >= 3) buf -= 3;
    }

    int scol = bn + wn;
    if (mode == 0) {
        int s   = scol / DIM;
        int rem = scol % DIM;
        int h   = rem / HD;
        int d0  = rem % HD;
        float* dst = (s == 0) ? g_Q : (s == 1) ? g_K : g_V;
        bool rnd = (s != 0);   // K and V consumed as tf32: pre-round them
        #pragma unroll
        for (int mt = 0; mt < 4; ++mt) {
            int r0 = bm + wm + mt * 16 + gr;
            int b  = r0 >> 11, n = r0 & (SEQ - 1);
            float* base = dst + ((size_t)(b * NH + h) * SEQ + n) * HD;
            #pragma unroll
            for (int nt = 0; nt < 4; ++nt) {
                int d = d0 + nt * 8 + 2 * qc;
                float v0 = acc[mt][nt][0], v1 = acc[mt][nt][1];
                float v2 = acc[mt][nt][2], v3 = acc[mt][nt][3];
                if (rnd) { v0 = rnaf(v0); v1 = rnaf(v1);
                           v2 = rnaf(v2); v3 = rnaf(v3); }
                *(float2*)(base + d) = make_float2(v0, v1);
                *(float2*)(base + 8 * HD + d) = make_float2(v2, v3);
            }
        }
    } else {
        #pragma unroll
        for (int mt = 0; mt < 4; ++mt) {
            int r0 = bm + wm + mt * 16 + gr;
            float* base = out + (size_t)r0 * DIM;
            #pragma unroll
            for (int nt = 0; nt < 4; ++nt) {
                int cb = scol + nt * 8 + 2 * qc;
                float2 bv = *(const float2*)(bias + cb);
                *(float2*)(base + cb) =
                    make_float2(acc[mt][nt][0] + bv.x, acc[mt][nt][1] + bv.y);
                *(float2*)(base + 8 * DIM + cb) =
                    make_float2(acc[mt][nt][2] + bv.x, acc[mt][nt][3] + bv.y);
            }
        }
    }
}

// ---------------------------------------------------------------------------
// Flash attention, mma.sync tf32, cp.async double-buffered K/V.
// K/V arrive pre-rounded -> zero cvt in the mainloop. AO written rounded.
// ---------------------------------------------------------------------------
#define ABC  64
#define KSTR 68
#define KBUF_WORDS (64 * KSTR)
#define V_OFF   (2 * KBUF_WORDS)
#define P_OFF   (4 * KBUF_WORDS)
#define ATT_SMEM ((4 * KBUF_WORDS + 128 * KSTR) * 4)   // 104448 bytes

__global__ __launch_bounds__(256) void attn_mma()
{
    extern __shared__ float sh[];
    uint32_t sbase = smem_u32(sh);
    float* Ps = sh + P_OFF;

    int bh  = blockIdx.y;
    int q0  = blockIdx.x * 128;
    int tid = threadIdx.x;
    int w   = tid >> 5, lane = tid & 31;
    int gr  = lane >> 2, qc = lane & 3;
    int wm  = w * 16;

    const float* Qb = g_Q + ((size_t)bh * SEQ + q0) * HD;
    const float* Kb = g_K + (size_t)bh * SEQ * HD;
    const float* Vb = g_V + (size_t)bh * SEQ * HD;

    // Q fragments, pre-scaled by SCALE*log2e, tf32-rounded (once per CTA).
    const float qs = SCALE * LOG2E;
    int r0 = wm + gr;
    uint32_t qf[8][4];
    #pragma unroll
    for (int kt = 0; kt < 8; ++kt) {
        int c = kt * 8 + qc;
        qf[kt][0] = f2tf32(Qb[(size_t)r0 * HD + c] * qs);
        qf[kt][1] = f2tf32(Qb[(size_t)(r0 + 8) * HD + c] * qs);
        qf[kt][2] = f2tf32(Qb[(size_t)r0 * HD + c + 4] * qs);
        qf[kt][3] = f2tf32(Qb[(size_t)(r0 + 8) * HD + c + 4] * qs);
    }

    const float* kg[4]; const float* vg[4]; uint32_t soff[4];
    #pragma unroll
    for (int i = 0; i < 4; ++i) {
        int slot = tid + i * 256;
        int key  = slot >> 4;
        int d4   = (slot & 15) * 4;
        kg[i]   = Kb + key * HD + d4;
        vg[i]   = Vb + key * HD + d4;
        soff[i] = (uint32_t)(key * KSTR + d4) * 4u;
    }

    float of[8][4];
    #pragma unroll
    for (int nt = 0; nt < 8; ++nt)
        #pragma unroll
        for (int i = 0; i < 4; ++i) of[nt][i] = 0.f;
    float m0 = -1e30f, m1 = -1e30f, l0 = 0.f, l1 = 0.f;

    const int NT = SEQ / ABC;   // 32

    #pragma unroll
    for (int i = 0; i < 4; ++i) {
        cpa16(sbase + soff[i], kg[i]);
        cpa16(sbase + V_OFF * 4 + soff[i], vg[i]);
    }
    CP_COMMIT();

    #pragma unroll 1
    for (int t = 0; t < NT; ++t) {
        if (t + 1 < NT) {
            uint32_t kb = sbase + (uint32_t)((t + 1) & 1) * KBUF_WORDS * 4u;
            size_t goff = (size_t)(t + 1) * ABC * HD;
            #pragma unroll
            for (int i = 0; i < 4; ++i) {
                cpa16(kb + soff[i], kg[i] + goff);
                cpa16(kb + V_OFF * 4 + soff[i], vg[i] + goff);
            }
            CP_COMMIT();
            CP_WAIT1();
        } else {
            CP_WAIT0();
        }
        __syncthreads();   // tile t visible

        const float* Kt = sh + (t & 1) * KBUF_WORDS;
        const float* Vt = Kt + V_OFF;

        // S = Q K^T  (K pre-rounded: plain LDS)
        float sf[8][4];
        #pragma unroll
        for (int nt = 0; nt < 8; ++nt)
            #pragma unroll
            for (int i = 0; i < 4; ++i) sf[nt][i] = 0.f;
        #pragma unroll
        for (int kt = 0; kt < 8; ++kt) {
            int k0 = kt * 8;
            #pragma unroll
            for (int nt = 0; nt < 8; ++nt) {
                const uint32_t* bp =
                    (const uint32_t*)(Kt + (nt * 8 + gr) * KSTR + k0 + qc);
                mma_tf32(sf[nt], qf[kt][0], qf[kt][1], qf[kt][2], qf[kt][3],
                         bp[0], bp[4]);
            }
        }

        // Online softmax (log2 domain, hardware ex2)
        float tm0 = -1e30f, tm1 = -1e30f;
        #pragma unroll
        for (int nt = 0; nt < 8; ++nt) {
            tm0 = fmaxf(tm0, fmaxf(sf[nt][0], sf[nt][1]));
            tm1 = fmaxf(tm1, fmaxf(sf[nt][2], sf[nt][3]));
        }
        tm0 = fmaxf(tm0, __shfl_xor_sync(0xffffffffu, tm0, 1));
        tm0 = fmaxf(tm0, __shfl_xor_sync(0xffffffffu, tm0, 2));
        tm1 = fmaxf(tm1, __shfl_xor_sync(0xffffffffu, tm1, 1));
        tm1 = fmaxf(tm1, __shfl_xor_sync(0xffffffffu, tm1, 2));

        float nm0 = fmaxf(m0, tm0), nm1 = fmaxf(m1, tm1);
        float c0 = ex2(m0 - nm0), c1 = ex2(m1 - nm1);
        m0 = nm0; m1 = nm1;

        float rs0 = 0.f, rs1 = 0.f;
        float* prow0 = Ps + (wm + gr) * KSTR + 2 * qc;
        float* prow1 = prow0 + 8 * KSTR;
        #pragma unroll
        for (int nt = 0; nt < 8; ++nt) {
            float p0 = rnaf(ex2(sf[nt][0] - nm0));
            float p1 = rnaf(ex2(sf[nt][1] - nm0));
            float p2 = rnaf(ex2(sf[nt][2] - nm1));
            float p3 = rnaf(ex2(sf[nt][3] - nm1));
            rs0 += p0 + p1;
            rs1 += p2 + p3;
            *(float2*)(prow0 + nt * 8) = make_float2(p0, p1);
            *(float2*)(prow1 + nt * 8) = make_float2(p2, p3);
        }
        rs0 += __shfl_xor_sync(0xffffffffu, rs0, 1);
        rs0 += __shfl_xor_sync(0xffffffffu, rs0, 2);
        rs1 += __shfl_xor_sync(0xffffffffu, rs1, 1);
        rs1 += __shfl_xor_sync(0xffffffffu, rs1, 2);
        l0 = l0 * c0 + rs0;
        l1 = l1 * c1 + rs1;

        #pragma unroll
        for (int nt = 0; nt < 8; ++nt) {
            of[nt][0] *= c0; of[nt][1] *= c0;
            of[nt][2] *= c1; of[nt][3] *= c1;
        }
        __syncwarp();   // P is warp-private

        // O += P V   (V pre-rounded, natural [key][dim]: column gather)
        #pragma unroll
        for (int kt = 0; kt < 8; ++kt) {
            int k0 = kt * 8;
            const uint32_t* ap =
                (const uint32_t*)(Ps + (wm + gr) * KSTR + k0 + qc);
            uint32_t a0 = ap[0];
            uint32_t a1 = ap[8 * KSTR];
            uint32_t a2 = ap[4];
            uint32_t a3 = ap[8 * KSTR + 4];
            #pragma unroll
            for (int nt = 0; nt < 8; ++nt) {
                const uint32_t* vp =
                    (const uint32_t*)(Vt + (k0 + qc) * KSTR + nt * 8 + gr);
                mma_tf32(of[nt], a0, a1, a2, a3, vp[0], vp[4 * KSTR]);
            }
        }
        __syncthreads();   // buffer reads done
    }

    // Epilogue: write AO tf32-rounded (consumed as tf32 by gemm_proj).
    float inv0 = 1.f / l0, inv1 = 1.f / l1;
    int b = bh / NH, h = bh % NH;
    int n0 = q0 + wm + gr;
    float* o0 = g_AO + ((size_t)(b * SEQ + n0)) * DIM + h * HD;
    float* o1 = g_AO + ((size_t)(b * SEQ + n0 + 8)) * DIM + h * HD;
    #pragma unroll
    for (int nt = 0; nt < 8; ++nt) {
        int d = nt * 8 + 2 * qc;
        *(float2*)(o0 + d) = make_float2(rnaf(of[nt][0] * inv0),
                                         rnaf(of[nt][1] * inv0));
        *(float2*)(o1 + d) = make_float2(rnaf(of[nt][2] * inv1),
                                         rnaf(of[nt][3] * inv1));
    }
}

// ---------------------------------------------------------------------------
extern "C" void kernel_launch(void* const* d_in, const int* in_sizes, int n_in,
                              void* d_out, int out_size)
{
    const float* x      = (const float*)d_in[0];
    const float* w_qkv  = (const float*)d_in[1];
    const float* w_proj = (const float*)d_in[2];
    const float* b_proj = (const float*)d_in[3];
    float* out = (float*)d_out;

    cudaFuncSetAttribute(gemm_mma, cudaFuncAttributeMaxDynamicSharedMemorySize,
                         GSM_BYTES);
    cudaFuncSetAttribute(attn_mma, cudaFuncAttributeMaxDynamicSharedMemorySize,
                         ATT_SMEM);

    int n4x = MROWS * DIM / 4, n4q = 3 * DIM * DIM / 4, n4p = DIM * DIM / 4;
    round_k<<<(n4x + 255) / 256, 256>>>(x, n4x, 0);
    round_k<<<(n4q + 255) / 256, 256>>>(w_qkv, n4q, 1);
    round_k<<<(n4p + 255) / 256, 256>>>(w_proj, n4p, 2);

    gemm_mma<<<dim3(MROWS/128, 3*DIM/128), 256, GSM_BYTES>>>(nullptr, nullptr, 0);
    attn_mma<<<dim3(SEQ/128, BH), 256, ATT_SMEM>>>();
    gemm_mma<<<dim3(MROWS/128, DIM/128), 256, GSM_BYTES>>>(b_proj, out, 1);
}